// round 11
// baseline (speedup 1.0000x reference)
#include <cuda_runtime.h>
#include <cuda_bf16.h>
#include <cstdint>
#include <math.h>

// Problem constants
#define Bb 4
#define Tt 2048
#define Cc 1024
#define Hh 16
#define Dd 64
#define BT (Bb*Tt)          // 8192
#define C3 (3*Cc)           // 3072

// ---------------------------------------------------------------------------
// Scratch (no cudaMalloc allowed)
// ---------------------------------------------------------------------------
__device__ __nv_bfloat16 g_qkvh[BT * C3];        // roped qkv hi
__device__ __nv_bfloat16 g_qkvl[BT * C3];        // roped qkv lo
__device__ __nv_bfloat16 g_xhi[BT * Cc];         // x split
__device__ __nv_bfloat16 g_xlo[BT * Cc];
__device__ __nv_bfloat16 g_wq_hi[C3 * Cc];       // W_qkv^T split  [N=3072][K=1024]
__device__ __nv_bfloat16 g_wq_lo[C3 * Cc];
__device__ __nv_bfloat16 g_wp_hi[Cc * Cc];       // W_proj^T split [N=1024][K=1024]
__device__ __nv_bfloat16 g_wp_lo[Cc * Cc];
__device__ __nv_bfloat16 g_yhi[BT * Cc];         // attention out split
__device__ __nv_bfloat16 g_ylo[BT * Cc];
__device__ float2 g_rope[Tt * 32];               // (sin, cos) per (t, i)

// ---------------------------------------------------------------------------
// Warp MMA helpers (plain sm_80+ features — no arch-suffix gating)
// ---------------------------------------------------------------------------
__device__ __forceinline__ uint32_t smem_to_u32(const void* p) {
    uint32_t a;
    asm("{ .reg .u64 t; cvta.to.shared.u64 t, %1; cvt.u32.u64 %0, t; }"
        : "=r"(a) : "l"(p));
    return a;
}
__device__ __forceinline__ void cp16(uint32_t d, const void* s) {
    asm volatile("cp.async.cg.shared.global [%0], [%1], 16;\n"
                 :: "r"(d), "l"(s) : "memory");
}
#define CP_COMMIT() asm volatile("cp.async.commit_group;" ::: "memory")
#define CP_WAIT(n)  asm volatile("cp.async.wait_group %0;" :: "n"(n) : "memory")

__device__ __forceinline__ void ldm_x4(uint32_t* r, uint32_t addr) {
    asm volatile("ldmatrix.sync.aligned.m8n8.x4.shared.b16 {%0,%1,%2,%3}, [%4];"
                 : "=r"(r[0]), "=r"(r[1]), "=r"(r[2]), "=r"(r[3]) : "r"(addr));
}
__device__ __forceinline__ void ldm_x4_t(uint32_t* r, uint32_t addr) {
    asm volatile("ldmatrix.sync.aligned.m8n8.x4.trans.shared.b16 {%0,%1,%2,%3}, [%4];"
                 : "=r"(r[0]), "=r"(r[1]), "=r"(r[2]), "=r"(r[3]) : "r"(addr));
}
__device__ __forceinline__ void mma_bf16(float* d, const uint32_t* a,
                                         const uint32_t* b) {
    asm volatile(
        "mma.sync.aligned.m16n8k16.row.col.f32.bf16.bf16.f32 "
        "{%0,%1,%2,%3}, {%4,%5,%6,%7}, {%8,%9}, {%0,%1,%2,%3};"
        : "+f"(d[0]), "+f"(d[1]), "+f"(d[2]), "+f"(d[3])
        : "r"(a[0]), "r"(a[1]), "r"(a[2]), "r"(a[3]), "r"(b[0]), "r"(b[1]));
}
// split two floats into packed bf16x2 hi + lo (residual)
__device__ __forceinline__ void split2(float a, float b, uint32_t& hi, uint32_t& lo) {
    __nv_bfloat16 ha = __float2bfloat16(a), hb = __float2bfloat16(b);
    __nv_bfloat16 la = __float2bfloat16(a - __bfloat162float(ha));
    __nv_bfloat16 lb = __float2bfloat16(b - __bfloat162float(hb));
    __nv_bfloat162 h2(ha, hb), l2(la, lb);
    hi = *(uint32_t*)&h2;
    lo = *(uint32_t*)&l2;
}

// ---------------------------------------------------------------------------
// RoPE sin/cos table: g_rope[t*32 + i] = (sin(t*freq_i), cos(t*freq_i))
// ---------------------------------------------------------------------------
__global__ void fill_rope() {
    int idx = blockIdx.x * blockDim.x + threadIdx.x;   // 0 .. 65535
    if (idx >= Tt * 32) return;
    int t = idx >> 5, i = idx & 31;
    float freq = exp2f(-(float)i * 0.4152410118609203f);
    float sn, cs;
    sincosf((float)t * freq, &sn, &cs);
    g_rope[idx] = make_float2(sn, cs);
}

// ---------------------------------------------------------------------------
// Split-bf16 HMMA GEMM.
// 3-stage cp.async pipeline + swizzled (pad-free) smem, 2 CTAs/SM.
// MODE 0: out = fp32 + bias.  MODE 1: rope(acc+bias) -> bf16 hi/lo out.
// CTA tile 128x128, BK=32, 8 warps (4 M x 2 N).
// ---------------------------------------------------------------------------
#define GPITCH 64
#define GSEC   8192                    // 128 rows * 64B
#define GSTAGE (4 * GSEC)              // 32768
#define GEMM_SMEM (3 * GSTAGE)         // 98304

template<int MODE>
__global__ __launch_bounds__(256, 2) void gemm_mma(
    const __nv_bfloat16* __restrict__ Ahi, const __nv_bfloat16* __restrict__ Alo,
    const __nv_bfloat16* __restrict__ Bhi, const __nv_bfloat16* __restrict__ Blo,
    const float* __restrict__ bias, float* __restrict__ outF,
    __nv_bfloat16* __restrict__ outH, __nv_bfloat16* __restrict__ outL, int N)
{
    extern __shared__ char sm[];
    const int tid = threadIdx.x, lane = tid & 31, wid = tid >> 5;
    const int warpM = wid >> 1, warpN = wid & 1;
    const int mBase = blockIdx.y * 128, nBase = blockIdx.x * 128;
    const uint32_t smBase = smem_to_u32(sm);

    // per-lane ldmatrix row bases + swizzle keys (row+16 preserves key)
    const int aRow = warpM * 32 + (lane & 15);
    const int aSel = (lane >> 4) & 1;
    const int aSwz = ((lane & 15) >> 1) & 3;
    const int bRow = warpN * 64 + (lane & 7) + ((lane >> 4) & 1) * 8;
    const int bSel = (lane >> 3) & 1;
    const int bSwz = ((((lane & 7) + ((lane >> 4) & 1) * 8)) >> 1) & 3;

    float acc[2][8][4];
    #pragma unroll
    for (int a = 0; a < 2; a++)
        #pragma unroll
        for (int q = 0; q < 8; q++)
            #pragma unroll
            for (int v = 0; v < 4; v++) acc[a][q][v] = 0.f;

    auto ldChunk = [&](int c, int stage) {
        uint32_t base = smBase + stage * GSTAGE;
        const int k0 = c * 32;
        #pragma unroll
        for (int i = 0; i < 2; i++) {
            int idx = i * 256 + tid;
            int row = idx >> 2, s = idx & 3;
            int ps = s ^ ((row >> 1) & 3);
            uint32_t d = base + row * GPITCH + ps * 16;
            size_t ga = (size_t)(mBase + row) * 1024 + k0 + s * 8;
            size_t gb = (size_t)(nBase + row) * 1024 + k0 + s * 8;
            cp16(d,            Ahi + ga);
            cp16(d + GSEC,     Alo + ga);
            cp16(d + 2 * GSEC, Bhi + gb);
            cp16(d + 3 * GSEC, Blo + gb);
        }
    };

    auto compute = [&](int stage) {
        uint32_t base = smBase + stage * GSTAGE;
        #pragma unroll
        for (int k16 = 0; k16 < 2; k16++) {
            const int aC = ((k16 * 2 + aSel) ^ aSwz) * 16;
            const int bC = ((k16 * 2 + bSel) ^ bSwz) * 16;
            uint32_t ah[2][4], al[2][4];
            #pragma unroll
            for (int a = 0; a < 2; a++) {
                uint32_t ad = base + (aRow + a * 16) * GPITCH + aC;
                ldm_x4(ah[a], ad);
                ldm_x4(al[a], ad + GSEC);
            }
            #pragma unroll
            for (int p = 0; p < 4; p++) {
                uint32_t bh[4], bl[4];
                uint32_t bd = base + 2 * GSEC + (bRow + p * 16) * GPITCH + bC;
                ldm_x4(bh, bd);
                ldm_x4(bl, bd + GSEC);
                #pragma unroll
                for (int a = 0; a < 2; a++) {
                    mma_bf16(acc[a][p * 2 + 0], ah[a], bh);
                    mma_bf16(acc[a][p * 2 + 0], ah[a], bl);
                    mma_bf16(acc[a][p * 2 + 0], al[a], bh);
                    mma_bf16(acc[a][p * 2 + 1], ah[a], bh + 2);
                    mma_bf16(acc[a][p * 2 + 1], ah[a], bl + 2);
                    mma_bf16(acc[a][p * 2 + 1], al[a], bh + 2);
                }
            }
        }
    };

    // 3-stage pipeline: chunks c, c+1 in flight; ONE sync per iteration.
    ldChunk(0, 0); CP_COMMIT();
    ldChunk(1, 1); CP_COMMIT();
    #pragma unroll 1
    for (int c = 0; c < 32; c++) {
        if (c == 31) { CP_WAIT(0); } else { CP_WAIT(1); }
        __syncthreads();
        if (c + 2 < 32) {
            ldChunk(c + 2, (c + 2) % 3);
            CP_COMMIT();
        }
        compute(c % 3);
    }

    // ---- epilogue ----
    const int r0 = mBase + warpM * 32 + (lane >> 2);
    #pragma unroll
    for (int a = 0; a < 2; a++)
        #pragma unroll
        for (int p = 0; p < 4; p++)
            #pragma unroll
            for (int h = 0; h < 2; h++) {
                const int col = nBase + warpN * 64 + p * 16 + h * 8 + (lane & 3) * 2;
                float2 bb = *(const float2*)(bias + col);
                #pragma unroll
                for (int r = 0; r < 2; r++) {
                    const int row = r0 + a * 16 + r * 8;
                    float v0 = acc[a][p * 2 + h][2 * r]     + bb.x;
                    float v1 = acc[a][p * 2 + h][2 * r + 1] + bb.y;
                    if (MODE == 1) {
                        if (col < 2048) {   // q or k section: RoPE (table lookup)
                            int i = (col & 63) >> 1;
                            int t = row & (Tt - 1);
                            float2 sc = g_rope[t * 32 + i];
                            float u0 = v0 * sc.y - v1 * sc.x;
                            float u1 = v0 * sc.x + v1 * sc.y;
                            v0 = u0; v1 = u1;
                        }
                        uint32_t hi, lo;
                        split2(v0, v1, hi, lo);
                        size_t off = (size_t)row * N + col;
                        *(uint32_t*)(outH + off) = hi;
                        *(uint32_t*)(outL + off) = lo;
                    } else {
                        float2 o = { v0, v1 };
                        *(float2*)(outF + (size_t)row * N + col) = o;
                    }
                }
            }
}

// ---------------------------------------------------------------------------
// HMMA flash attention (unchanged — known good).
// ---------------------------------------------------------------------------
#define FP 144
#define FQSZ (64 * FP)
#define FKV  (4 * FQSZ)
#define FLASH_SMEM (2 * FQSZ + 2 * FKV)   // 92160

__global__ __launch_bounds__(128) void flash_mma(
    const __nv_bfloat16* __restrict__ qh, const __nv_bfloat16* __restrict__ ql,
    __nv_bfloat16* __restrict__ yh, __nv_bfloat16* __restrict__ yl)
{
    extern __shared__ char sm[];
    const int tid = threadIdx.x, lane = tid & 31, wid = tid >> 5;
    const int bh = blockIdx.y, b = bh >> 4, h = bh & 15;
    const int qt = (gridDim.x - 1) - blockIdx.x;
    const int q0 = qt * 64;
    const size_t grow = (size_t)b * Tt;

    const uint32_t QH = smem_to_u32(sm);
    const uint32_t KV0 = QH + 2 * FQSZ;

    {
        #pragma unroll
        for (int i = 0; i < 4; i++) {
            int idx = i * 128 + tid;
            int row = idx >> 3, ch = idx & 7;
            uint32_t d = QH + row * FP + ch * 16;
            size_t src = (grow + q0 + row) * C3 + h * Dd + ch * 8;
            cp16(d,        qh + src);
            cp16(d + FQSZ, ql + src);
        }
    }
    auto prefetchKV = [&](int kt, int buf) {
        uint32_t base = KV0 + buf * FKV;
        #pragma unroll
        for (int i = 0; i < 4; i++) {
            int idx = i * 128 + tid;
            int row = idx >> 3, ch = idx & 7;
            uint32_t d = base + row * FP + ch * 16;
            size_t srcK = (grow + kt * 64 + row) * C3 + Cc + h * Dd + ch * 8;
            size_t srcV = srcK + Cc;
            cp16(d,            qh + srcK);
            cp16(d + FQSZ,     ql + srcK);
            cp16(d + 2 * FQSZ, qh + srcV);
            cp16(d + 3 * FQSZ, ql + srcV);
        }
    };
    prefetchKV(0, 0);
    CP_COMMIT();
    CP_WAIT(0);
    __syncthreads();

    uint32_t qhf[4][4], qlf[4][4];
    {
        uint32_t a = QH + (wid * 16 + (lane & 15)) * FP + ((lane >> 4) & 1) * 16;
        #pragma unroll
        for (int k16 = 0; k16 < 4; k16++) {
            ldm_x4(qhf[k16], a + k16 * 32);
            ldm_x4(qlf[k16], a + FQSZ + k16 * 32);
        }
    }

    float o[8][4];
    float mrow[2] = {-1e30f, -1e30f}, lrow[2] = {0.f, 0.f};
    #pragma unroll
    for (int d = 0; d < 8; d++)
        #pragma unroll
        for (int v = 0; v < 4; v++) o[d][v] = 0.f;

    #pragma unroll 1
    for (int kt = 0; kt <= qt; kt++) {
        const int buf = kt & 1;
        if (kt > 0) { CP_WAIT(0); __syncthreads(); }
        if (kt < qt) { prefetchKV(kt + 1, buf ^ 1); CP_COMMIT(); }

        const uint32_t KB = KV0 + buf * FKV;

        float s[8][4];
        #pragma unroll
        for (int n = 0; n < 8; n++)
            #pragma unroll
            for (int v = 0; v < 4; v++) s[n][v] = 0.f;

        #pragma unroll
        for (int k16 = 0; k16 < 4; k16++) {
            #pragma unroll
            for (int np = 0; np < 4; np++) {
                uint32_t kh4[4], kl4[4];
                uint32_t ad = KB + (np * 16 + (lane & 7) + ((lane >> 4) & 1) * 8) * FP
                            + ((lane >> 3) & 1) * 16 + k16 * 32;
                ldm_x4(kh4, ad);
                ldm_x4(kl4, ad + FQSZ);
                mma_bf16(s[2 * np],     qhf[k16], kh4);
                mma_bf16(s[2 * np],     qhf[k16], kl4);
                mma_bf16(s[2 * np],     qlf[k16], kh4);
                mma_bf16(s[2 * np + 1], qhf[k16], kh4 + 2);
                mma_bf16(s[2 * np + 1], qhf[k16], kl4 + 2);
                mma_bf16(s[2 * np + 1], qlf[k16], kh4 + 2);
            }
        }

        #pragma unroll
        for (int n = 0; n < 8; n++)
            #pragma unroll
            for (int v = 0; v < 4; v++) s[n][v] *= 0.125f;
        if (kt == qt) {
            const int row0 = wid * 16 + (lane >> 2);
            #pragma unroll
            for (int n = 0; n < 8; n++) {
                int cb = n * 8 + (lane & 3) * 2;
                #pragma unroll
                for (int r = 0; r < 2; r++)
                    #pragma unroll
                    for (int j = 0; j < 2; j++)
                        if (cb + j > row0 + r * 8) s[n][2 * r + j] = -1e30f;
            }
        }

        #pragma unroll
        for (int r = 0; r < 2; r++) {
            float mx = -1e30f;
            #pragma unroll
            for (int n = 0; n < 8; n++)
                mx = fmaxf(mx, fmaxf(s[n][2 * r], s[n][2 * r + 1]));
            mx = fmaxf(mx, __shfl_xor_sync(0xffffffffu, mx, 1));
            mx = fmaxf(mx, __shfl_xor_sync(0xffffffffu, mx, 2));
            float mnew = fmaxf(mrow[r], mx);
            float alpha = __expf(mrow[r] - mnew);
            float sum = 0.f;
            #pragma unroll
            for (int n = 0; n < 8; n++) {
                float p0 = __expf(s[n][2 * r] - mnew);
                float p1 = __expf(s[n][2 * r + 1] - mnew);
                s[n][2 * r] = p0; s[n][2 * r + 1] = p1;
                sum += p0 + p1;
            }
            sum += __shfl_xor_sync(0xffffffffu, sum, 1);
            sum += __shfl_xor_sync(0xffffffffu, sum, 2);
            lrow[r] = lrow[r] * alpha + sum;
            mrow[r] = mnew;
            #pragma unroll
            for (int d = 0; d < 8; d++) {
                o[d][2 * r] *= alpha;
                o[d][2 * r + 1] *= alpha;
            }
        }

        #pragma unroll
        for (int k16 = 0; k16 < 4; k16++) {
            uint32_t phi[4], plo[4];
            const int t0 = 2 * k16, t1 = t0 + 1;
            split2(s[t0][0], s[t0][1], phi[0], plo[0]);
            split2(s[t0][2], s[t0][3], phi[1], plo[1]);
            split2(s[t1][0], s[t1][1], phi[2], plo[2]);
            split2(s[t1][2], s[t1][3], phi[3], plo[3]);
            #pragma unroll
            for (int dp = 0; dp < 4; dp++) {
                uint32_t vh4[4], vl4[4];
                uint32_t ad = KB + 2 * FQSZ
                            + (k16 * 16 + (lane & 7) + ((lane >> 3) & 1) * 8) * FP
                            + ((lane >> 4) & 1) * 16 + dp * 32;
                ldm_x4_t(vh4, ad);
                ldm_x4_t(vl4, ad + FQSZ);
                mma_bf16(o[2 * dp],     phi, vh4);
                mma_bf16(o[2 * dp],     phi, vl4);
                mma_bf16(o[2 * dp],     plo, vh4);
                mma_bf16(o[2 * dp + 1], phi, vh4 + 2);
                mma_bf16(o[2 * dp + 1], phi, vl4 + 2);
                mma_bf16(o[2 * dp + 1], plo, vh4 + 2);
            }
        }
    }

    #pragma unroll
    for (int r = 0; r < 2; r++) {
        const int t = q0 + wid * 16 + (lane >> 2) + r * 8;
        const float inv = 1.f / lrow[r];
        const size_t ro = (grow + t) * Cc + h * Dd;
        #pragma unroll
        for (int d = 0; d < 8; d++) {
            int col = d * 8 + (lane & 3) * 2;
            float v0 = o[d][2 * r] * inv;
            float v1 = o[d][2 * r + 1] * inv;
            uint32_t hi, lo;
            split2(v0, v1, hi, lo);
            *(uint32_t*)(yh + ro + col) = hi;
            *(uint32_t*)(yl + ro + col) = lo;
        }
    }
}

// ---------------------------------------------------------------------------
// fp32 -> (hi, lo) bf16 split
// ---------------------------------------------------------------------------
__global__ __launch_bounds__(256) void split_bf16(
    const float* __restrict__ x, __nv_bfloat16* __restrict__ hi,
    __nv_bfloat16* __restrict__ lo, int n4)
{
    int i = blockIdx.x * blockDim.x + threadIdx.x;
    if (i >= n4) return;
    float4 v = ((const float4*)x)[i];
    __nv_bfloat16 h0 = __float2bfloat16(v.x);
    __nv_bfloat16 h1 = __float2bfloat16(v.y);
    __nv_bfloat16 h2 = __float2bfloat16(v.z);
    __nv_bfloat16 h3 = __float2bfloat16(v.w);
    __nv_bfloat16 l0 = __float2bfloat16(v.x - __bfloat162float(h0));
    __nv_bfloat16 l1 = __float2bfloat16(v.y - __bfloat162float(h1));
    __nv_bfloat16 l2 = __float2bfloat16(v.z - __bfloat162float(h2));
    __nv_bfloat16 l3 = __float2bfloat16(v.w - __bfloat162float(h3));
    __nv_bfloat162* hp = (__nv_bfloat162*)(hi + i * 4);
    __nv_bfloat162* lp = (__nv_bfloat162*)(lo + i * 4);
    hp[0] = __nv_bfloat162(h0, h1); hp[1] = __nv_bfloat162(h2, h3);
    lp[0] = __nv_bfloat162(l0, l1); lp[1] = __nv_bfloat162(l2, l3);
}

// ---------------------------------------------------------------------------
// W [K, N] fp32 -> Wt hi/lo bf16 [N, K] (transpose + split)
// ---------------------------------------------------------------------------
__global__ __launch_bounds__(256) void transpose_split(
    const float* __restrict__ W, __nv_bfloat16* __restrict__ thi,
    __nv_bfloat16* __restrict__ tlo, int K, int N)
{
    __shared__ float t[32][33];
    const int k0 = blockIdx.y * 32, n0 = blockIdx.x * 32;
    const int x = threadIdx.x, y = threadIdx.y;   // block (32, 8)
    #pragma unroll
    for (int r = 0; r < 32; r += 8)
        t[y + r][x] = W[(size_t)(k0 + y + r) * N + n0 + x];
    __syncthreads();
    #pragma unroll
    for (int r = 0; r < 32; r += 8) {
        float v = t[x][y + r];
        __nv_bfloat16 h = __float2bfloat16(v);
        __nv_bfloat16 l = __float2bfloat16(v - __bfloat162float(h));
        size_t o = (size_t)(n0 + y + r) * K + k0 + x;
        thi[o] = h; tlo[o] = l;
    }
}

// ---------------------------------------------------------------------------
extern "C" void kernel_launch(void* const* d_in, const int* in_sizes, int n_in,
                              void* d_out, int out_size)
{
    const float* x      = (const float*)d_in[0];
    const float* W_qkv  = (const float*)d_in[1];
    const float* b_qkv  = (const float*)d_in[2];
    const float* W_proj = (const float*)d_in[3];
    const float* b_proj = (const float*)d_in[4];
    float* out = (float*)d_out;

    void *qh_p, *ql_p, *xh_p, *xl_p, *wqh_p, *wql_p, *wph_p, *wpl_p,
         *yh_p, *yl_p;
    cudaGetSymbolAddress(&qh_p, g_qkvh);
    cudaGetSymbolAddress(&ql_p, g_qkvl);
    cudaGetSymbolAddress(&xh_p, g_xhi);
    cudaGetSymbolAddress(&xl_p, g_xlo);
    cudaGetSymbolAddress(&wqh_p, g_wq_hi);
    cudaGetSymbolAddress(&wql_p, g_wq_lo);
    cudaGetSymbolAddress(&wph_p, g_wp_hi);
    cudaGetSymbolAddress(&wpl_p, g_wp_lo);
    cudaGetSymbolAddress(&yh_p, g_yhi);
    cudaGetSymbolAddress(&yl_p, g_ylo);

    cudaFuncSetAttribute(gemm_mma<0>,
        cudaFuncAttributeMaxDynamicSharedMemorySize, GEMM_SMEM);
    cudaFuncSetAttribute(gemm_mma<1>,
        cudaFuncAttributeMaxDynamicSharedMemorySize, GEMM_SMEM);
    cudaFuncSetAttribute(flash_mma,
        cudaFuncAttributeMaxDynamicSharedMemorySize, FLASH_SMEM);

    // 0) RoPE sin/cos table
    fill_rope<<<(Tt * 32 + 255) / 256, 256>>>();
    // 1) Split x -> bf16 hi/lo
    split_bf16<<<(BT * Cc / 4 + 255) / 256, 256>>>(
        x, (__nv_bfloat16*)xh_p, (__nv_bfloat16*)xl_p, BT * Cc / 4);
    // 2) Transpose+split weights
    {
        dim3 g(C3 / 32, Cc / 32);
        transpose_split<<<g, dim3(32, 8)>>>(W_qkv,
            (__nv_bfloat16*)wqh_p, (__nv_bfloat16*)wql_p, Cc, C3);
    }
    {
        dim3 g(Cc / 32, Cc / 32);
        transpose_split<<<g, dim3(32, 8)>>>(W_proj,
            (__nv_bfloat16*)wph_p, (__nv_bfloat16*)wpl_p, Cc, Cc);
    }
    // 3) QKV GEMM + fused RoPE (table) + split -> qkvh/qkvl bf16
    {
        dim3 grid(C3 / 128, BT / 128);
        gemm_mma<1><<<grid, 256, GEMM_SMEM>>>(
            (const __nv_bfloat16*)xh_p, (const __nv_bfloat16*)xl_p,
            (const __nv_bfloat16*)wqh_p, (const __nv_bfloat16*)wql_p,
            b_qkv, nullptr,
            (__nv_bfloat16*)qh_p, (__nv_bfloat16*)ql_p, C3);
    }
    // 4) HMMA flash attention -> y hi/lo bf16
    {
        dim3 grid(Tt / 64, Bb * Hh);
        flash_mma<<<grid, 128, FLASH_SMEM>>>(
            (const __nv_bfloat16*)qh_p, (const __nv_bfloat16*)ql_p,
            (__nv_bfloat16*)yh_p, (__nv_bfloat16*)yl_p);
    }
    // 5) Output projection -> out fp32
    {
        dim3 grid(Cc / 128, BT / 128);
        gemm_mma<0><<<grid, 256, GEMM_SMEM>>>(
            (const __nv_bfloat16*)yh_p, (const __nv_bfloat16*)yl_p,
            (const __nv_bfloat16*)wph_p, (const __nv_bfloat16*)wpl_p,
            b_proj, out, nullptr, nullptr, Cc);
    }
}

// round 12
// speedup vs baseline: 1.0034x; 1.0034x over previous
#include <cuda_runtime.h>
#include <cuda_bf16.h>
#include <cstdint>
#include <math.h>

// Problem constants
#define Bb 4
#define Tt 2048
#define Cc 1024
#define Hh 16
#define Dd 64
#define BT (Bb*Tt)          // 8192
#define C3 (3*Cc)           // 3072

// ---------------------------------------------------------------------------
// Scratch (no cudaMalloc allowed)
// ---------------------------------------------------------------------------
__device__ __nv_bfloat16 g_qkvh[BT * C3];        // roped qkv hi
__device__ __nv_bfloat16 g_qkvl[BT * C3];        // roped qkv lo
__device__ __nv_bfloat16 g_xhi[BT * Cc];         // x split
__device__ __nv_bfloat16 g_xlo[BT * Cc];
__device__ __nv_bfloat16 g_wq_hi[C3 * Cc];       // W_qkv^T split  [N=3072][K=1024]
__device__ __nv_bfloat16 g_wq_lo[C3 * Cc];
__device__ __nv_bfloat16 g_wp_hi[Cc * Cc];       // W_proj^T split [N=1024][K=1024]
__device__ __nv_bfloat16 g_wp_lo[Cc * Cc];
__device__ __nv_bfloat16 g_yhi[BT * Cc];         // attention out split
__device__ __nv_bfloat16 g_ylo[BT * Cc];
__device__ float2 g_rope[Tt * 32];               // (sin, cos) per (t, i)

// ---------------------------------------------------------------------------
// Warp MMA helpers (plain sm_80+ features — no arch-suffix gating)
// ---------------------------------------------------------------------------
__device__ __forceinline__ uint32_t smem_to_u32(const void* p) {
    uint32_t a;
    asm("{ .reg .u64 t; cvta.to.shared.u64 t, %1; cvt.u32.u64 %0, t; }"
        : "=r"(a) : "l"(p));
    return a;
}
__device__ __forceinline__ void cp16(uint32_t d, const void* s) {
    asm volatile("cp.async.cg.shared.global [%0], [%1], 16;\n"
                 :: "r"(d), "l"(s) : "memory");
}
#define CP_COMMIT() asm volatile("cp.async.commit_group;" ::: "memory")
#define CP_WAIT(n)  asm volatile("cp.async.wait_group %0;" :: "n"(n) : "memory")

__device__ __forceinline__ void ldm_x4(uint32_t* r, uint32_t addr) {
    asm volatile("ldmatrix.sync.aligned.m8n8.x4.shared.b16 {%0,%1,%2,%3}, [%4];"
                 : "=r"(r[0]), "=r"(r[1]), "=r"(r[2]), "=r"(r[3]) : "r"(addr));
}
__device__ __forceinline__ void ldm_x4_t(uint32_t* r, uint32_t addr) {
    asm volatile("ldmatrix.sync.aligned.m8n8.x4.trans.shared.b16 {%0,%1,%2,%3}, [%4];"
                 : "=r"(r[0]), "=r"(r[1]), "=r"(r[2]), "=r"(r[3]) : "r"(addr));
}
__device__ __forceinline__ void mma_bf16(float* d, const uint32_t* a,
                                         const uint32_t* b) {
    asm volatile(
        "mma.sync.aligned.m16n8k16.row.col.f32.bf16.bf16.f32 "
        "{%0,%1,%2,%3}, {%4,%5,%6,%7}, {%8,%9}, {%0,%1,%2,%3};"
        : "+f"(d[0]), "+f"(d[1]), "+f"(d[2]), "+f"(d[3])
        : "r"(a[0]), "r"(a[1]), "r"(a[2]), "r"(a[3]), "r"(b[0]), "r"(b[1]));
}
// split two floats into packed bf16x2 hi + lo (residual)
__device__ __forceinline__ void split2(float a, float b, uint32_t& hi, uint32_t& lo) {
    __nv_bfloat16 ha = __float2bfloat16(a), hb = __float2bfloat16(b);
    __nv_bfloat16 la = __float2bfloat16(a - __bfloat162float(ha));
    __nv_bfloat16 lb = __float2bfloat16(b - __bfloat162float(hb));
    __nv_bfloat162 h2(ha, hb), l2(la, lb);
    hi = *(uint32_t*)&h2;
    lo = *(uint32_t*)&l2;
}

// ---------------------------------------------------------------------------
// RoPE sin/cos table
// ---------------------------------------------------------------------------
__global__ void fill_rope() {
    int idx = blockIdx.x * blockDim.x + threadIdx.x;
    if (idx >= Tt * 32) return;
    int t = idx >> 5, i = idx & 31;
    float freq = exp2f(-(float)i * 0.4152410118609203f);
    float sn, cs;
    sincosf((float)t * freq, &sn, &cs);
    g_rope[idx] = make_float2(sn, cs);
}

// ---------------------------------------------------------------------------
// Split-bf16 HMMA GEMM (unchanged — known good, R9 shape).
// ---------------------------------------------------------------------------
#define GPITCH 64
#define GSEC   8192
#define GSTAGE (4 * GSEC)
#define GEMM_SMEM (3 * GSTAGE)         // 98304

template<int MODE>
__global__ __launch_bounds__(256, 2) void gemm_mma(
    const __nv_bfloat16* __restrict__ Ahi, const __nv_bfloat16* __restrict__ Alo,
    const __nv_bfloat16* __restrict__ Bhi, const __nv_bfloat16* __restrict__ Blo,
    const float* __restrict__ bias, float* __restrict__ outF,
    __nv_bfloat16* __restrict__ outH, __nv_bfloat16* __restrict__ outL, int N)
{
    extern __shared__ char sm[];
    const int tid = threadIdx.x, lane = tid & 31, wid = tid >> 5;
    const int warpM = wid >> 1, warpN = wid & 1;
    const int mBase = blockIdx.y * 128, nBase = blockIdx.x * 128;
    const uint32_t smBase = smem_to_u32(sm);

    const int aRow = warpM * 32 + (lane & 15);
    const int aSel = (lane >> 4) & 1;
    const int aSwz = ((lane & 15) >> 1) & 3;
    const int bRow = warpN * 64 + (lane & 7) + ((lane >> 4) & 1) * 8;
    const int bSel = (lane >> 3) & 1;
    const int bSwz = ((((lane & 7) + ((lane >> 4) & 1) * 8)) >> 1) & 3;

    float acc[2][8][4];
    #pragma unroll
    for (int a = 0; a < 2; a++)
        #pragma unroll
        for (int q = 0; q < 8; q++)
            #pragma unroll
            for (int v = 0; v < 4; v++) acc[a][q][v] = 0.f;

    auto ldChunk = [&](int c, int stage) {
        uint32_t base = smBase + stage * GSTAGE;
        const int k0 = c * 32;
        #pragma unroll
        for (int i = 0; i < 2; i++) {
            int idx = i * 256 + tid;
            int row = idx >> 2, s = idx & 3;
            int ps = s ^ ((row >> 1) & 3);
            uint32_t d = base + row * GPITCH + ps * 16;
            size_t ga = (size_t)(mBase + row) * 1024 + k0 + s * 8;
            size_t gb = (size_t)(nBase + row) * 1024 + k0 + s * 8;
            cp16(d,            Ahi + ga);
            cp16(d + GSEC,     Alo + ga);
            cp16(d + 2 * GSEC, Bhi + gb);
            cp16(d + 3 * GSEC, Blo + gb);
        }
    };

    auto compute = [&](int stage) {
        uint32_t base = smBase + stage * GSTAGE;
        #pragma unroll
        for (int k16 = 0; k16 < 2; k16++) {
            const int aC = ((k16 * 2 + aSel) ^ aSwz) * 16;
            const int bC = ((k16 * 2 + bSel) ^ bSwz) * 16;
            uint32_t ah[2][4], al[2][4];
            #pragma unroll
            for (int a = 0; a < 2; a++) {
                uint32_t ad = base + (aRow + a * 16) * GPITCH + aC;
                ldm_x4(ah[a], ad);
                ldm_x4(al[a], ad + GSEC);
            }
            #pragma unroll
            for (int p = 0; p < 4; p++) {
                uint32_t bh[4], bl[4];
                uint32_t bd = base + 2 * GSEC + (bRow + p * 16) * GPITCH + bC;
                ldm_x4(bh, bd);
                ldm_x4(bl, bd + GSEC);
                #pragma unroll
                for (int a = 0; a < 2; a++) {
                    mma_bf16(acc[a][p * 2 + 0], ah[a], bh);
                    mma_bf16(acc[a][p * 2 + 0], ah[a], bl);
                    mma_bf16(acc[a][p * 2 + 0], al[a], bh);
                    mma_bf16(acc[a][p * 2 + 1], ah[a], bh + 2);
                    mma_bf16(acc[a][p * 2 + 1], ah[a], bl + 2);
                    mma_bf16(acc[a][p * 2 + 1], al[a], bh + 2);
                }
            }
        }
    };

    ldChunk(0, 0); CP_COMMIT();
    ldChunk(1, 1); CP_COMMIT();
    #pragma unroll 1
    for (int c = 0; c < 32; c++) {
        if (c == 31) { CP_WAIT(0); } else { CP_WAIT(1); }
        __syncthreads();
        if (c + 2 < 32) {
            ldChunk(c + 2, (c + 2) % 3);
            CP_COMMIT();
        }
        compute(c % 3);
    }

    const int r0 = mBase + warpM * 32 + (lane >> 2);
    #pragma unroll
    for (int a = 0; a < 2; a++)
        #pragma unroll
        for (int p = 0; p < 4; p++)
            #pragma unroll
            for (int h = 0; h < 2; h++) {
                const int col = nBase + warpN * 64 + p * 16 + h * 8 + (lane & 3) * 2;
                float2 bb = *(const float2*)(bias + col);
                #pragma unroll
                for (int r = 0; r < 2; r++) {
                    const int row = r0 + a * 16 + r * 8;
                    float v0 = acc[a][p * 2 + h][2 * r]     + bb.x;
                    float v1 = acc[a][p * 2 + h][2 * r + 1] + bb.y;
                    if (MODE == 1) {
                        if (col < 2048) {
                            int i = (col & 63) >> 1;
                            int t = row & (Tt - 1);
                            float2 sc = g_rope[t * 32 + i];
                            float u0 = v0 * sc.y - v1 * sc.x;
                            float u1 = v0 * sc.x + v1 * sc.y;
                            v0 = u0; v1 = u1;
                        }
                        uint32_t hi, lo;
                        split2(v0, v1, hi, lo);
                        size_t off = (size_t)row * N + col;
                        *(uint32_t*)(outH + off) = hi;
                        *(uint32_t*)(outL + off) = lo;
                    } else {
                        float2 o = { v0, v1 };
                        *(float2*)(outF + (size_t)row * N + col) = o;
                    }
                }
            }
}

// ---------------------------------------------------------------------------
// HMMA flash attention, Br=128 (8 warps x m16), Bc=64, 256 threads.
// K/V tiles serve 128 q-rows -> half the L2 traffic of Br=64.
// Warps skip fully-masked tiles (still participate in prefetch/sync).
// ---------------------------------------------------------------------------
#define FP 144
#define FQSZ (128 * FP)               // 18432 (one Q array: hi or lo)
#define FKSZ (64 * FP)                // 9216  (one K/V array)
#define FKV  (4 * FKSZ)               // 36864 per stage
#define FLASH_SMEM (2 * FQSZ + 2 * FKV)   // 110592

__global__ __launch_bounds__(256, 2) void flash_mma(
    const __nv_bfloat16* __restrict__ qh, const __nv_bfloat16* __restrict__ ql,
    __nv_bfloat16* __restrict__ yh, __nv_bfloat16* __restrict__ yl)
{
    extern __shared__ char sm[];
    const int tid = threadIdx.x, lane = tid & 31, wid = tid >> 5;
    const int bh = blockIdx.y, b = bh >> 4, h = bh & 15;
    const int qt = (gridDim.x - 1) - blockIdx.x;   // heavy CTAs first
    const int q0 = qt * 128;
    const int ntiles = 2 * qt + 2;
    const size_t grow = (size_t)b * Tt;

    const uint32_t QH = smem_to_u32(sm);
    const uint32_t KV0 = QH + 2 * FQSZ;

    // prefetch Q (128 rows, hi+lo)
    {
        #pragma unroll
        for (int i = 0; i < 4; i++) {
            int idx = i * 256 + tid;          // 0..1023
            int row = idx >> 3, ch = idx & 7;
            uint32_t d = QH + row * FP + ch * 16;
            size_t src = (grow + q0 + row) * C3 + h * Dd + ch * 8;
            cp16(d,        qh + src);
            cp16(d + FQSZ, ql + src);
        }
    }
    auto prefetchKV = [&](int kt, int buf) {
        uint32_t base = KV0 + buf * FKV;
        #pragma unroll
        for (int i = 0; i < 2; i++) {
            int idx = i * 256 + tid;          // 0..511
            int row = idx >> 3, ch = idx & 7;
            uint32_t d = base + row * FP + ch * 16;
            size_t srcK = (grow + kt * 64 + row) * C3 + Cc + h * Dd + ch * 8;
            size_t srcV = srcK + Cc;
            cp16(d,            qh + srcK);
            cp16(d + FKSZ,     ql + srcK);
            cp16(d + 2 * FKSZ, qh + srcV);
            cp16(d + 3 * FKSZ, ql + srcV);
        }
    };
    prefetchKV(0, 0);
    CP_COMMIT();
    CP_WAIT(0);
    __syncthreads();

    // Q fragments for this warp's 16 rows (held in regs)
    uint32_t qhf[4][4], qlf[4][4];
    {
        uint32_t a = QH + (wid * 16 + (lane & 15)) * FP + ((lane >> 4) & 1) * 16;
        #pragma unroll
        for (int k16 = 0; k16 < 4; k16++) {
            ldm_x4(qhf[k16], a + k16 * 32);
            ldm_x4(qlf[k16], a + FQSZ + k16 * 32);
        }
    }

    float o[8][4];
    float mrow[2] = {-1e30f, -1e30f}, lrow[2] = {0.f, 0.f};
    #pragma unroll
    for (int d = 0; d < 8; d++)
        #pragma unroll
        for (int v = 0; v < 4; v++) o[d][v] = 0.f;

    const int rowMin = q0 + wid * 16;          // warp's first global row
    const int row0g = rowMin + (lane >> 2);    // thread's first global row

    #pragma unroll 1
    for (int kt = 0; kt < ntiles; kt++) {
        const int buf = kt & 1;
        if (kt > 0) { CP_WAIT(0); __syncthreads(); }
        if (kt + 1 < ntiles) { prefetchKV(kt + 1, buf ^ 1); CP_COMMIT(); }

        // Skip tiles entirely above this warp's rows (fully masked)
        if (kt * 64 > rowMin + 15) continue;

        const uint32_t KB = KV0 + buf * FKV;

        // ---- S = Q K^T (split) ----
        float s[8][4];
        #pragma unroll
        for (int n = 0; n < 8; n++)
            #pragma unroll
            for (int v = 0; v < 4; v++) s[n][v] = 0.f;

        #pragma unroll
        for (int k16 = 0; k16 < 4; k16++) {
            #pragma unroll
            for (int np = 0; np < 4; np++) {
                uint32_t kh4[4], kl4[4];
                uint32_t ad = KB + (np * 16 + (lane & 7) + ((lane >> 4) & 1) * 8) * FP
                            + ((lane >> 3) & 1) * 16 + k16 * 32;
                ldm_x4(kh4, ad);
                ldm_x4(kl4, ad + FKSZ);
                mma_bf16(s[2 * np],     qhf[k16], kh4);
                mma_bf16(s[2 * np],     qhf[k16], kl4);
                mma_bf16(s[2 * np],     qlf[k16], kh4);
                mma_bf16(s[2 * np + 1], qhf[k16], kh4 + 2);
                mma_bf16(s[2 * np + 1], qhf[k16], kl4 + 2);
                mma_bf16(s[2 * np + 1], qlf[k16], kh4 + 2);
            }
        }

        // ---- scale + causal mask (global col > global row) ----
        #pragma unroll
        for (int n = 0; n < 8; n++)
            #pragma unroll
            for (int v = 0; v < 4; v++) s[n][v] *= 0.125f;
        if (kt * 64 + 63 > rowMin) {   // tile touches/crosses the diagonal
            #pragma unroll
            for (int n = 0; n < 8; n++) {
                int colg = kt * 64 + n * 8 + (lane & 3) * 2;
                #pragma unroll
                for (int r = 0; r < 2; r++)
                    #pragma unroll
                    for (int j = 0; j < 2; j++)
                        if (colg + j > row0g + r * 8) s[n][2 * r + j] = -1e30f;
            }
        }

        // ---- online softmax (2 rows per thread) ----
        #pragma unroll
        for (int r = 0; r < 2; r++) {
            float mx = -1e30f;
            #pragma unroll
            for (int n = 0; n < 8; n++)
                mx = fmaxf(mx, fmaxf(s[n][2 * r], s[n][2 * r + 1]));
            mx = fmaxf(mx, __shfl_xor_sync(0xffffffffu, mx, 1));
            mx = fmaxf(mx, __shfl_xor_sync(0xffffffffu, mx, 2));
            float mnew = fmaxf(mrow[r], mx);
            float alpha = __expf(mrow[r] - mnew);
            float sum = 0.f;
            #pragma unroll
            for (int n = 0; n < 8; n++) {
                float p0 = __expf(s[n][2 * r] - mnew);
                float p1 = __expf(s[n][2 * r + 1] - mnew);
                s[n][2 * r] = p0; s[n][2 * r + 1] = p1;
                sum += p0 + p1;
            }
            sum += __shfl_xor_sync(0xffffffffu, sum, 1);
            sum += __shfl_xor_sync(0xffffffffu, sum, 2);
            lrow[r] = lrow[r] * alpha + sum;
            mrow[r] = mnew;
            #pragma unroll
            for (int d = 0; d < 8; d++) {
                o[d][2 * r] *= alpha;
                o[d][2 * r + 1] *= alpha;
            }
        }

        // ---- O += P V ----
        #pragma unroll
        for (int k16 = 0; k16 < 4; k16++) {
            uint32_t phi[4], plo[4];
            const int t0 = 2 * k16, t1 = t0 + 1;
            split2(s[t0][0], s[t0][1], phi[0], plo[0]);
            split2(s[t0][2], s[t0][3], phi[1], plo[1]);
            split2(s[t1][0], s[t1][1], phi[2], plo[2]);
            split2(s[t1][2], s[t1][3], phi[3], plo[3]);
            #pragma unroll
            for (int dp = 0; dp < 4; dp++) {
                uint32_t vh4[4], vl4[4];
                uint32_t ad = KB + 2 * FKSZ
                            + (k16 * 16 + (lane & 7) + ((lane >> 3) & 1) * 8) * FP
                            + ((lane >> 4) & 1) * 16 + dp * 32;
                ldm_x4_t(vh4, ad);
                ldm_x4_t(vl4, ad + FKSZ);
                mma_bf16(o[2 * dp],     phi, vh4);
                mma_bf16(o[2 * dp],     phi, vl4);
                mma_bf16(o[2 * dp],     plo, vh4);
                mma_bf16(o[2 * dp + 1], phi, vh4 + 2);
                mma_bf16(o[2 * dp + 1], phi, vl4 + 2);
                mma_bf16(o[2 * dp + 1], plo, vh4 + 2);
            }
        }
    }

    // ---- epilogue ----
    #pragma unroll
    for (int r = 0; r < 2; r++) {
        const int t = q0 + wid * 16 + (lane >> 2) + r * 8;
        const float inv = 1.f / lrow[r];
        const size_t ro = (grow + t) * Cc + h * Dd;
        #pragma unroll
        for (int d = 0; d < 8; d++) {
            int col = d * 8 + (lane & 3) * 2;
            float v0 = o[d][2 * r] * inv;
            float v1 = o[d][2 * r + 1] * inv;
            uint32_t hi, lo;
            split2(v0, v1, hi, lo);
            *(uint32_t*)(yh + ro + col) = hi;
            *(uint32_t*)(yl + ro + col) = lo;
        }
    }
}

// ---------------------------------------------------------------------------
// fp32 -> (hi, lo) bf16 split
// ---------------------------------------------------------------------------
__global__ __launch_bounds__(256) void split_bf16(
    const float* __restrict__ x, __nv_bfloat16* __restrict__ hi,
    __nv_bfloat16* __restrict__ lo, int n4)
{
    int i = blockIdx.x * blockDim.x + threadIdx.x;
    if (i >= n4) return;
    float4 v = ((const float4*)x)[i];
    __nv_bfloat16 h0 = __float2bfloat16(v.x);
    __nv_bfloat16 h1 = __float2bfloat16(v.y);
    __nv_bfloat16 h2 = __float2bfloat16(v.z);
    __nv_bfloat16 h3 = __float2bfloat16(v.w);
    __nv_bfloat16 l0 = __float2bfloat16(v.x - __bfloat162float(h0));
    __nv_bfloat16 l1 = __float2bfloat16(v.y - __bfloat162float(h1));
    __nv_bfloat16 l2 = __float2bfloat16(v.z - __bfloat162float(h2));
    __nv_bfloat16 l3 = __float2bfloat16(v.w - __bfloat162float(h3));
    __nv_bfloat162* hp = (__nv_bfloat162*)(hi + i * 4);
    __nv_bfloat162* lp = (__nv_bfloat162*)(lo + i * 4);
    hp[0] = __nv_bfloat162(h0, h1); hp[1] = __nv_bfloat162(h2, h3);
    lp[0] = __nv_bfloat162(l0, l1); lp[1] = __nv_bfloat162(l2, l3);
}

// ---------------------------------------------------------------------------
// W [K, N] fp32 -> Wt hi/lo bf16 [N, K] (transpose + split)
// ---------------------------------------------------------------------------
__global__ __launch_bounds__(256) void transpose_split(
    const float* __restrict__ W, __nv_bfloat16* __restrict__ thi,
    __nv_bfloat16* __restrict__ tlo, int K, int N)
{
    __shared__ float t[32][33];
    const int k0 = blockIdx.y * 32, n0 = blockIdx.x * 32;
    const int x = threadIdx.x, y = threadIdx.y;   // block (32, 8)
    #pragma unroll
    for (int r = 0; r < 32; r += 8)
        t[y + r][x] = W[(size_t)(k0 + y + r) * N + n0 + x];
    __syncthreads();
    #pragma unroll
    for (int r = 0; r < 32; r += 8) {
        float v = t[x][y + r];
        __nv_bfloat16 h = __float2bfloat16(v);
        __nv_bfloat16 l = __float2bfloat16(v - __bfloat162float(h));
        size_t o = (size_t)(n0 + y + r) * K + k0 + x;
        thi[o] = h; tlo[o] = l;
    }
}

// ---------------------------------------------------------------------------
extern "C" void kernel_launch(void* const* d_in, const int* in_sizes, int n_in,
                              void* d_out, int out_size)
{
    const float* x      = (const float*)d_in[0];
    const float* W_qkv  = (const float*)d_in[1];
    const float* b_qkv  = (const float*)d_in[2];
    const float* W_proj = (const float*)d_in[3];
    const float* b_proj = (const float*)d_in[4];
    float* out = (float*)d_out;

    void *qh_p, *ql_p, *xh_p, *xl_p, *wqh_p, *wql_p, *wph_p, *wpl_p,
         *yh_p, *yl_p;
    cudaGetSymbolAddress(&qh_p, g_qkvh);
    cudaGetSymbolAddress(&ql_p, g_qkvl);
    cudaGetSymbolAddress(&xh_p, g_xhi);
    cudaGetSymbolAddress(&xl_p, g_xlo);
    cudaGetSymbolAddress(&wqh_p, g_wq_hi);
    cudaGetSymbolAddress(&wql_p, g_wq_lo);
    cudaGetSymbolAddress(&wph_p, g_wp_hi);
    cudaGetSymbolAddress(&wpl_p, g_wp_lo);
    cudaGetSymbolAddress(&yh_p, g_yhi);
    cudaGetSymbolAddress(&yl_p, g_ylo);

    cudaFuncSetAttribute(gemm_mma<0>,
        cudaFuncAttributeMaxDynamicSharedMemorySize, GEMM_SMEM);
    cudaFuncSetAttribute(gemm_mma<1>,
        cudaFuncAttributeMaxDynamicSharedMemorySize, GEMM_SMEM);
    cudaFuncSetAttribute(flash_mma,
        cudaFuncAttributeMaxDynamicSharedMemorySize, FLASH_SMEM);

    // 0) RoPE sin/cos table
    fill_rope<<<(Tt * 32 + 255) / 256, 256>>>();
    // 1) Split x -> bf16 hi/lo
    split_bf16<<<(BT * Cc / 4 + 255) / 256, 256>>>(
        x, (__nv_bfloat16*)xh_p, (__nv_bfloat16*)xl_p, BT * Cc / 4);
    // 2) Transpose+split weights
    {
        dim3 g(C3 / 32, Cc / 32);
        transpose_split<<<g, dim3(32, 8)>>>(W_qkv,
            (__nv_bfloat16*)wqh_p, (__nv_bfloat16*)wql_p, Cc, C3);
    }
    {
        dim3 g(Cc / 32, Cc / 32);
        transpose_split<<<g, dim3(32, 8)>>>(W_proj,
            (__nv_bfloat16*)wph_p, (__nv_bfloat16*)wpl_p, Cc, Cc);
    }
    // 3) QKV GEMM + fused RoPE (table) + split -> qkvh/qkvl bf16
    {
        dim3 grid(C3 / 128, BT / 128);
        gemm_mma<1><<<grid, 256, GEMM_SMEM>>>(
            (const __nv_bfloat16*)xh_p, (const __nv_bfloat16*)xl_p,
            (const __nv_bfloat16*)wqh_p, (const __nv_bfloat16*)wql_p,
            b_qkv, nullptr,
            (__nv_bfloat16*)qh_p, (__nv_bfloat16*)ql_p, C3);
    }
    // 4) HMMA flash attention (Br=128) -> y hi/lo bf16
    {
        dim3 grid(Tt / 128, Bb * Hh);
        flash_mma<<<grid, 256, FLASH_SMEM>>>(
            (const __nv_bfloat16*)qh_p, (const __nv_bfloat16*)ql_p,
            (__nv_bfloat16*)yh_p, (__nv_bfloat16*)yl_p);
    }
    // 5) Output projection -> out fp32
    {
        dim3 grid(Cc / 128, BT / 128);
        gemm_mma<0><<<grid, 256, GEMM_SMEM>>>(
            (const __nv_bfloat16*)yh_p, (const __nv_bfloat16*)yl_p,
            (const __nv_bfloat16*)wph_p, (const __nv_bfloat16*)wpl_p,
            b_proj, out, nullptr, nullptr, Cc);
    }
}

// round 14
// speedup vs baseline: 1.0156x; 1.0121x over previous
#include <cuda_runtime.h>
#include <cuda_bf16.h>
#include <cstdint>
#include <math.h>

// Problem constants
#define Bb 4
#define Tt 2048
#define Cc 1024
#define Hh 16
#define Dd 64
#define BT (Bb*Tt)          // 8192
#define C3 (3*Cc)           // 3072

// 0.125 * log2(e): folded into K so softmax runs in exp2 domain
#define KSCALE 0.18033688011112042f

// ---------------------------------------------------------------------------
// Scratch (no cudaMalloc allowed)
// ---------------------------------------------------------------------------
__device__ __nv_bfloat16 g_qkvh[BT * C3];        // roped qkv hi (K pre-scaled)
__device__ __nv_bfloat16 g_qkvl[BT * C3];        // roped qkv lo
__device__ __nv_bfloat16 g_xhi[BT * Cc];         // x split
__device__ __nv_bfloat16 g_xlo[BT * Cc];
__device__ __nv_bfloat16 g_wq_hi[C3 * Cc];       // W_qkv^T split  [N=3072][K=1024]
__device__ __nv_bfloat16 g_wq_lo[C3 * Cc];
__device__ __nv_bfloat16 g_wp_hi[Cc * Cc];       // W_proj^T split [N=1024][K=1024]
__device__ __nv_bfloat16 g_wp_lo[Cc * Cc];
__device__ __nv_bfloat16 g_yhi[BT * Cc];         // attention out split
__device__ __nv_bfloat16 g_ylo[BT * Cc];
__device__ float2 g_rope[Tt * 32];               // (sin, cos) per (t, i)

// ---------------------------------------------------------------------------
// Warp MMA helpers (plain sm_80+ features — no arch-suffix gating)
// ---------------------------------------------------------------------------
__device__ __forceinline__ uint32_t smem_to_u32(const void* p) {
    uint32_t a;
    asm("{ .reg .u64 t; cvta.to.shared.u64 t, %1; cvt.u32.u64 %0, t; }"
        : "=r"(a) : "l"(p));
    return a;
}
__device__ __forceinline__ void cp16(uint32_t d, const void* s) {
    asm volatile("cp.async.cg.shared.global [%0], [%1], 16;\n"
                 :: "r"(d), "l"(s) : "memory");
}
#define CP_COMMIT() asm volatile("cp.async.commit_group;" ::: "memory")
#define CP_WAIT(n)  asm volatile("cp.async.wait_group %0;" :: "n"(n) : "memory")

__device__ __forceinline__ void ldm_x4(uint32_t* r, uint32_t addr) {
    asm volatile("ldmatrix.sync.aligned.m8n8.x4.shared.b16 {%0,%1,%2,%3}, [%4];"
                 : "=r"(r[0]), "=r"(r[1]), "=r"(r[2]), "=r"(r[3]) : "r"(addr));
}
__device__ __forceinline__ void ldm_x4_t(uint32_t* r, uint32_t addr) {
    asm volatile("ldmatrix.sync.aligned.m8n8.x4.trans.shared.b16 {%0,%1,%2,%3}, [%4];"
                 : "=r"(r[0]), "=r"(r[1]), "=r"(r[2]), "=r"(r[3]) : "r"(addr));
}
__device__ __forceinline__ void mma_bf16(float* d, const uint32_t* a,
                                         const uint32_t* b) {
    asm volatile(
        "mma.sync.aligned.m16n8k16.row.col.f32.bf16.bf16.f32 "
        "{%0,%1,%2,%3}, {%4,%5,%6,%7}, {%8,%9}, {%0,%1,%2,%3};"
        : "+f"(d[0]), "+f"(d[1]), "+f"(d[2]), "+f"(d[3])
        : "r"(a[0]), "r"(a[1]), "r"(a[2]), "r"(a[3]), "r"(b[0]), "r"(b[1]));
}
// split two floats into packed bf16x2 hi + lo (residual)
__device__ __forceinline__ void split2(float a, float b, uint32_t& hi, uint32_t& lo) {
    __nv_bfloat16 ha = __float2bfloat16(a), hb = __float2bfloat16(b);
    __nv_bfloat16 la = __float2bfloat16(a - __bfloat162float(ha));
    __nv_bfloat16 lb = __float2bfloat16(b - __bfloat162float(hb));
    __nv_bfloat162 h2(ha, hb), l2(la, lb);
    hi = *(uint32_t*)&h2;
    lo = *(uint32_t*)&l2;
}

// ---------------------------------------------------------------------------
// RoPE sin/cos table
// ---------------------------------------------------------------------------
__global__ void fill_rope() {
    int idx = blockIdx.x * blockDim.x + threadIdx.x;
    if (idx >= Tt * 32) return;
    int t = idx >> 5, i = idx & 31;
    float freq = exp2f(-(float)i * 0.4152410118609203f);
    float sn, cs;
    sincosf((float)t * freq, &sn, &cs);
    g_rope[idx] = make_float2(sn, cs);
}

// ---------------------------------------------------------------------------
// Split-bf16 HMMA GEMM (R9 mainloop — known good).
// MODE 0: out = fp32 + bias.
// MODE 1: rope(acc+bias); K section additionally scaled by KSCALE; bf16 hi/lo.
// ---------------------------------------------------------------------------
#define GPITCH 64
#define GSEC   8192
#define GSTAGE (4 * GSEC)
#define GEMM_SMEM (3 * GSTAGE)         // 98304

template<int MODE>
__global__ __launch_bounds__(256, 2) void gemm_mma(
    const __nv_bfloat16* __restrict__ Ahi, const __nv_bfloat16* __restrict__ Alo,
    const __nv_bfloat16* __restrict__ Bhi, const __nv_bfloat16* __restrict__ Blo,
    const float* __restrict__ bias, float* __restrict__ outF,
    __nv_bfloat16* __restrict__ outH, __nv_bfloat16* __restrict__ outL, int N)
{
    extern __shared__ char sm[];
    const int tid = threadIdx.x, lane = tid & 31, wid = tid >> 5;
    const int warpM = wid >> 1, warpN = wid & 1;
    const int mBase = blockIdx.y * 128, nBase = blockIdx.x * 128;
    const uint32_t smBase = smem_to_u32(sm);

    const int aRow = warpM * 32 + (lane & 15);
    const int aSel = (lane >> 4) & 1;
    const int aSwz = ((lane & 15) >> 1) & 3;
    const int bRow = warpN * 64 + (lane & 7) + ((lane >> 4) & 1) * 8;
    const int bSel = (lane >> 3) & 1;
    const int bSwz = ((((lane & 7) + ((lane >> 4) & 1) * 8)) >> 1) & 3;

    float acc[2][8][4];
    #pragma unroll
    for (int a = 0; a < 2; a++)
        #pragma unroll
        for (int q = 0; q < 8; q++)
            #pragma unroll
            for (int v = 0; v < 4; v++) acc[a][q][v] = 0.f;

    auto ldChunk = [&](int c, int stage) {
        uint32_t base = smBase + stage * GSTAGE;
        const int k0 = c * 32;
        #pragma unroll
        for (int i = 0; i < 2; i++) {
            int idx = i * 256 + tid;
            int row = idx >> 2, s = idx & 3;
            int ps = s ^ ((row >> 1) & 3);
            uint32_t d = base + row * GPITCH + ps * 16;
            size_t ga = (size_t)(mBase + row) * 1024 + k0 + s * 8;
            size_t gb = (size_t)(nBase + row) * 1024 + k0 + s * 8;
            cp16(d,            Ahi + ga);
            cp16(d + GSEC,     Alo + ga);
            cp16(d + 2 * GSEC, Bhi + gb);
            cp16(d + 3 * GSEC, Blo + gb);
        }
    };

    auto compute = [&](int stage) {
        uint32_t base = smBase + stage * GSTAGE;
        #pragma unroll
        for (int k16 = 0; k16 < 2; k16++) {
            const int aC = ((k16 * 2 + aSel) ^ aSwz) * 16;
            const int bC = ((k16 * 2 + bSel) ^ bSwz) * 16;
            uint32_t ah[2][4], al[2][4];
            #pragma unroll
            for (int a = 0; a < 2; a++) {
                uint32_t ad = base + (aRow + a * 16) * GPITCH + aC;
                ldm_x4(ah[a], ad);
                ldm_x4(al[a], ad + GSEC);
            }
            #pragma unroll
            for (int p = 0; p < 4; p++) {
                uint32_t bh[4], bl[4];
                uint32_t bd = base + 2 * GSEC + (bRow + p * 16) * GPITCH + bC;
                ldm_x4(bh, bd);
                ldm_x4(bl, bd + GSEC);
                #pragma unroll
                for (int a = 0; a < 2; a++) {
                    mma_bf16(acc[a][p * 2 + 0], ah[a], bh);
                    mma_bf16(acc[a][p * 2 + 0], ah[a], bl);
                    mma_bf16(acc[a][p * 2 + 0], al[a], bh);
                    mma_bf16(acc[a][p * 2 + 1], ah[a], bh + 2);
                    mma_bf16(acc[a][p * 2 + 1], ah[a], bl + 2);
                    mma_bf16(acc[a][p * 2 + 1], al[a], bh + 2);
                }
            }
        }
    };

    ldChunk(0, 0); CP_COMMIT();
    ldChunk(1, 1); CP_COMMIT();
    #pragma unroll 1
    for (int c = 0; c < 32; c++) {
        if (c == 31) { CP_WAIT(0); } else { CP_WAIT(1); }
        __syncthreads();
        if (c + 2 < 32) {
            ldChunk(c + 2, (c + 2) % 3);
            CP_COMMIT();
        }
        compute(c % 3);
    }

    const int r0 = mBase + warpM * 32 + (lane >> 2);
    #pragma unroll
    for (int a = 0; a < 2; a++)
        #pragma unroll
        for (int p = 0; p < 4; p++)
            #pragma unroll
            for (int h = 0; h < 2; h++) {
                const int col = nBase + warpN * 64 + p * 16 + h * 8 + (lane & 3) * 2;
                float2 bb = *(const float2*)(bias + col);
                #pragma unroll
                for (int r = 0; r < 2; r++) {
                    const int row = r0 + a * 16 + r * 8;
                    float v0 = acc[a][p * 2 + h][2 * r]     + bb.x;
                    float v1 = acc[a][p * 2 + h][2 * r + 1] + bb.y;
                    if (MODE == 1) {
                        if (col < 2048) {   // q or k: RoPE
                            int i = (col & 63) >> 1;
                            int t = row & (Tt - 1);
                            float2 sc = g_rope[t * 32 + i];
                            float u0 = v0 * sc.y - v1 * sc.x;
                            float u1 = v0 * sc.x + v1 * sc.y;
                            v0 = u0; v1 = u1;
                            if (col >= 1024) {   // k: fold softmax scale (exp2 domain)
                                v0 *= KSCALE; v1 *= KSCALE;
                            }
                        }
                        uint32_t hi, lo;
                        split2(v0, v1, hi, lo);
                        size_t off = (size_t)row * N + col;
                        *(uint32_t*)(outH + off) = hi;
                        *(uint32_t*)(outL + off) = lo;
                    } else {
                        float2 o = { v0, v1 };
                        *(float2*)(outF + (size_t)row * N + col) = o;
                    }
                }
            }
}

// ---------------------------------------------------------------------------
// HMMA flash attention, Br=128, Bc=64, 256 threads, 2 CTAs/SM.
// S in exp2 domain (KSCALE folded into K). PV keeps the FULL 3-combo split
// (phi*Vhi + phi*Vlo + plo*Vhi) — dropping plo costs 1.2e-3 rel_err (R13).
// ---------------------------------------------------------------------------
#define FP 144
#define FQSZ (128 * FP)               // 18432
#define FKSZ (64 * FP)                // 9216
#define FKV  (4 * FKSZ)               // 36864 per stage
#define FLASH_SMEM (2 * FQSZ + 2 * FKV)   // 110592

__global__ __launch_bounds__(256, 2) void flash_mma(
    const __nv_bfloat16* __restrict__ qh, const __nv_bfloat16* __restrict__ ql,
    __nv_bfloat16* __restrict__ yh, __nv_bfloat16* __restrict__ yl)
{
    extern __shared__ char sm[];
    const int tid = threadIdx.x, lane = tid & 31, wid = tid >> 5;
    const int bh = blockIdx.y, b = bh >> 4, h = bh & 15;
    const int qt = (gridDim.x - 1) - blockIdx.x;   // heavy CTAs first
    const int q0 = qt * 128;
    const int ntiles = 2 * qt + 2;
    const size_t grow = (size_t)b * Tt;

    const uint32_t QH = smem_to_u32(sm);
    const uint32_t KV0 = QH + 2 * FQSZ;

    {
        #pragma unroll
        for (int i = 0; i < 4; i++) {
            int idx = i * 256 + tid;
            int row = idx >> 3, ch = idx & 7;
            uint32_t d = QH + row * FP + ch * 16;
            size_t src = (grow + q0 + row) * C3 + h * Dd + ch * 8;
            cp16(d,        qh + src);
            cp16(d + FQSZ, ql + src);
        }
    }
    auto prefetchKV = [&](int kt, int buf) {
        uint32_t base = KV0 + buf * FKV;
        #pragma unroll
        for (int i = 0; i < 2; i++) {
            int idx = i * 256 + tid;
            int row = idx >> 3, ch = idx & 7;
            uint32_t d = base + row * FP + ch * 16;
            size_t srcK = (grow + kt * 64 + row) * C3 + Cc + h * Dd + ch * 8;
            size_t srcV = srcK + Cc;
            cp16(d,            qh + srcK);
            cp16(d + FKSZ,     ql + srcK);
            cp16(d + 2 * FKSZ, qh + srcV);
            cp16(d + 3 * FKSZ, ql + srcV);
        }
    };
    prefetchKV(0, 0);
    CP_COMMIT();
    CP_WAIT(0);
    __syncthreads();

    uint32_t qhf[4][4], qlf[4][4];
    {
        uint32_t a = QH + (wid * 16 + (lane & 15)) * FP + ((lane >> 4) & 1) * 16;
        #pragma unroll
        for (int k16 = 0; k16 < 4; k16++) {
            ldm_x4(qhf[k16], a + k16 * 32);
            ldm_x4(qlf[k16], a + FQSZ + k16 * 32);
        }
    }

    float o[8][4];
    float mrow[2] = {-1e30f, -1e30f}, lrow[2] = {0.f, 0.f};
    #pragma unroll
    for (int d = 0; d < 8; d++)
        #pragma unroll
        for (int v = 0; v < 4; v++) o[d][v] = 0.f;

    const int rowMin = q0 + wid * 16;
    const int row0g = rowMin + (lane >> 2);

    #pragma unroll 1
    for (int kt = 0; kt < ntiles; kt++) {
        const int buf = kt & 1;
        if (kt > 0) { CP_WAIT(0); __syncthreads(); }
        if (kt + 1 < ntiles) { prefetchKV(kt + 1, buf ^ 1); CP_COMMIT(); }

        if (kt * 64 > rowMin + 15) continue;   // fully masked for this warp

        const uint32_t KB = KV0 + buf * FKV;

        // ---- S = Q K^T (split; S already in exp2 domain) ----
        float s[8][4];
        #pragma unroll
        for (int n = 0; n < 8; n++)
            #pragma unroll
            for (int v = 0; v < 4; v++) s[n][v] = 0.f;

        #pragma unroll
        for (int k16 = 0; k16 < 4; k16++) {
            #pragma unroll
            for (int np = 0; np < 4; np++) {
                uint32_t kh4[4], kl4[4];
                uint32_t ad = KB + (np * 16 + (lane & 7) + ((lane >> 4) & 1) * 8) * FP
                            + ((lane >> 3) & 1) * 16 + k16 * 32;
                ldm_x4(kh4, ad);
                ldm_x4(kl4, ad + FKSZ);
                mma_bf16(s[2 * np],     qhf[k16], kh4);
                mma_bf16(s[2 * np],     qhf[k16], kl4);
                mma_bf16(s[2 * np],     qlf[k16], kh4);
                mma_bf16(s[2 * np + 1], qhf[k16], kh4 + 2);
                mma_bf16(s[2 * np + 1], qhf[k16], kl4 + 2);
                mma_bf16(s[2 * np + 1], qlf[k16], kh4 + 2);
            }
        }

        // ---- causal mask ----
        if (kt * 64 + 63 > rowMin) {
            #pragma unroll
            for (int n = 0; n < 8; n++) {
                int colg = kt * 64 + n * 8 + (lane & 3) * 2;
                #pragma unroll
                for (int r = 0; r < 2; r++)
                    #pragma unroll
                    for (int j = 0; j < 2; j++)
                        if (colg + j > row0g + r * 8) s[n][2 * r + j] = -1e30f;
            }
        }

        // ---- online softmax in exp2 domain ----
        #pragma unroll
        for (int r = 0; r < 2; r++) {
            float mx = -1e30f;
            #pragma unroll
            for (int n = 0; n < 8; n++)
                mx = fmaxf(mx, fmaxf(s[n][2 * r], s[n][2 * r + 1]));
            mx = fmaxf(mx, __shfl_xor_sync(0xffffffffu, mx, 1));
            mx = fmaxf(mx, __shfl_xor_sync(0xffffffffu, mx, 2));
            float mnew = fmaxf(mrow[r], mx);
            float alpha = exp2f(mrow[r] - mnew);
            float sum = 0.f;
            #pragma unroll
            for (int n = 0; n < 8; n++) {
                float p0 = exp2f(s[n][2 * r] - mnew);
                float p1 = exp2f(s[n][2 * r + 1] - mnew);
                s[n][2 * r] = p0; s[n][2 * r + 1] = p1;
                sum += p0 + p1;
            }
            sum += __shfl_xor_sync(0xffffffffu, sum, 1);
            sum += __shfl_xor_sync(0xffffffffu, sum, 2);
            lrow[r] = lrow[r] * alpha + sum;
            mrow[r] = mnew;
            #pragma unroll
            for (int d = 0; d < 8; d++) {
                o[d][2 * r] *= alpha;
                o[d][2 * r + 1] *= alpha;
            }
        }

        // ---- O += P V (full 3-combo split) ----
        #pragma unroll
        for (int k16 = 0; k16 < 4; k16++) {
            uint32_t phi[4], plo[4];
            const int t0 = 2 * k16, t1 = t0 + 1;
            split2(s[t0][0], s[t0][1], phi[0], plo[0]);
            split2(s[t0][2], s[t0][3], phi[1], plo[1]);
            split2(s[t1][0], s[t1][1], phi[2], plo[2]);
            split2(s[t1][2], s[t1][3], phi[3], plo[3]);
            #pragma unroll
            for (int dp = 0; dp < 4; dp++) {
                uint32_t vh4[4], vl4[4];
                uint32_t ad = KB + 2 * FKSZ
                            + (k16 * 16 + (lane & 7) + ((lane >> 3) & 1) * 8) * FP
                            + ((lane >> 4) & 1) * 16 + dp * 32;
                ldm_x4_t(vh4, ad);
                ldm_x4_t(vl4, ad + FKSZ);
                mma_bf16(o[2 * dp],     phi, vh4);
                mma_bf16(o[2 * dp],     phi, vl4);
                mma_bf16(o[2 * dp],     plo, vh4);
                mma_bf16(o[2 * dp + 1], phi, vh4 + 2);
                mma_bf16(o[2 * dp + 1], phi, vl4 + 2);
                mma_bf16(o[2 * dp + 1], plo, vh4 + 2);
            }
        }
    }

    // ---- epilogue ----
    #pragma unroll
    for (int r = 0; r < 2; r++) {
        const int t = q0 + wid * 16 + (lane >> 2) + r * 8;
        const float inv = 1.f / lrow[r];
        const size_t ro = (grow + t) * Cc + h * Dd;
        #pragma unroll
        for (int d = 0; d < 8; d++) {
            int col = d * 8 + (lane & 3) * 2;
            float v0 = o[d][2 * r] * inv;
            float v1 = o[d][2 * r + 1] * inv;
            uint32_t hi, lo;
            split2(v0, v1, hi, lo);
            *(uint32_t*)(yh + ro + col) = hi;
            *(uint32_t*)(yl + ro + col) = lo;
        }
    }
}

// ---------------------------------------------------------------------------
// fp32 -> (hi, lo) bf16 split
// ---------------------------------------------------------------------------
__global__ __launch_bounds__(256) void split_bf16(
    const float* __restrict__ x, __nv_bfloat16* __restrict__ hi,
    __nv_bfloat16* __restrict__ lo, int n4)
{
    int i = blockIdx.x * blockDim.x + threadIdx.x;
    if (i >= n4) return;
    float4 v = ((const float4*)x)[i];
    __nv_bfloat16 h0 = __float2bfloat16(v.x);
    __nv_bfloat16 h1 = __float2bfloat16(v.y);
    __nv_bfloat16 h2 = __float2bfloat16(v.z);
    __nv_bfloat16 h3 = __float2bfloat16(v.w);
    __nv_bfloat16 l0 = __float2bfloat16(v.x - __bfloat162float(h0));
    __nv_bfloat16 l1 = __float2bfloat16(v.y - __bfloat162float(h1));
    __nv_bfloat16 l2 = __float2bfloat16(v.z - __bfloat162float(h2));
    __nv_bfloat16 l3 = __float2bfloat16(v.w - __bfloat162float(h3));
    __nv_bfloat162* hp = (__nv_bfloat162*)(hi + i * 4);
    __nv_bfloat162* lp = (__nv_bfloat162*)(lo + i * 4);
    hp[0] = __nv_bfloat162(h0, h1); hp[1] = __nv_bfloat162(h2, h3);
    lp[0] = __nv_bfloat162(l0, l1); lp[1] = __nv_bfloat162(l2, l3);
}

// ---------------------------------------------------------------------------
// W [K, N] fp32 -> Wt hi/lo bf16 [N, K] (transpose + split)
// ---------------------------------------------------------------------------
__global__ __launch_bounds__(256) void transpose_split(
    const float* __restrict__ W, __nv_bfloat16* __restrict__ thi,
    __nv_bfloat16* __restrict__ tlo, int K, int N)
{
    __shared__ float t[32][33];
    const int k0 = blockIdx.y * 32, n0 = blockIdx.x * 32;
    const int x = threadIdx.x, y = threadIdx.y;   // block (32, 8)
    #pragma unroll
    for (int r = 0; r < 32; r += 8)
        t[y + r][x] = W[(size_t)(k0 + y + r) * N + n0 + x];
    __syncthreads();
    #pragma unroll
    for (int r = 0; r < 32; r += 8) {
        float v = t[x][y + r];
        __nv_bfloat16 h = __float2bfloat16(v);
        __nv_bfloat16 l = __float2bfloat16(v - __bfloat162float(h));
        size_t o = (size_t)(n0 + y + r) * K + k0 + x;
        thi[o] = h; tlo[o] = l;
    }
}

// ---------------------------------------------------------------------------
extern "C" void kernel_launch(void* const* d_in, const int* in_sizes, int n_in,
                              void* d_out, int out_size)
{
    const float* x      = (const float*)d_in[0];
    const float* W_qkv  = (const float*)d_in[1];
    const float* b_qkv  = (const float*)d_in[2];
    const float* W_proj = (const float*)d_in[3];
    const float* b_proj = (const float*)d_in[4];
    float* out = (float*)d_out;

    void *qh_p, *ql_p, *xh_p, *xl_p, *wqh_p, *wql_p, *wph_p, *wpl_p,
         *yh_p, *yl_p;
    cudaGetSymbolAddress(&qh_p, g_qkvh);
    cudaGetSymbolAddress(&ql_p, g_qkvl);
    cudaGetSymbolAddress(&xh_p, g_xhi);
    cudaGetSymbolAddress(&xl_p, g_xlo);
    cudaGetSymbolAddress(&wqh_p, g_wq_hi);
    cudaGetSymbolAddress(&wql_p, g_wq_lo);
    cudaGetSymbolAddress(&wph_p, g_wp_hi);
    cudaGetSymbolAddress(&wpl_p, g_wp_lo);
    cudaGetSymbolAddress(&yh_p, g_yhi);
    cudaGetSymbolAddress(&yl_p, g_ylo);

    cudaFuncSetAttribute(gemm_mma<0>,
        cudaFuncAttributeMaxDynamicSharedMemorySize, GEMM_SMEM);
    cudaFuncSetAttribute(gemm_mma<1>,
        cudaFuncAttributeMaxDynamicSharedMemorySize, GEMM_SMEM);
    cudaFuncSetAttribute(flash_mma,
        cudaFuncAttributeMaxDynamicSharedMemorySize, FLASH_SMEM);

    // 0) RoPE sin/cos table
    fill_rope<<<(Tt * 32 + 255) / 256, 256>>>();
    // 1) Split x -> bf16 hi/lo
    split_bf16<<<(BT * Cc / 4 + 255) / 256, 256>>>(
        x, (__nv_bfloat16*)xh_p, (__nv_bfloat16*)xl_p, BT * Cc / 4);
    // 2) Transpose+split weights
    {
        dim3 g(C3 / 32, Cc / 32);
        transpose_split<<<g, dim3(32, 8)>>>(W_qkv,
            (__nv_bfloat16*)wqh_p, (__nv_bfloat16*)wql_p, Cc, C3);
    }
    {
        dim3 g(Cc / 32, Cc / 32);
        transpose_split<<<g, dim3(32, 8)>>>(W_proj,
            (__nv_bfloat16*)wph_p, (__nv_bfloat16*)wpl_p, Cc, Cc);
    }
    // 3) QKV GEMM + fused RoPE + K-scale + split -> qkvh/qkvl bf16
    {
        dim3 grid(C3 / 128, BT / 128);
        gemm_mma<1><<<grid, 256, GEMM_SMEM>>>(
            (const __nv_bfloat16*)xh_p, (const __nv_bfloat16*)xl_p,
            (const __nv_bfloat16*)wqh_p, (const __nv_bfloat16*)wql_p,
            b_qkv, nullptr,
            (__nv_bfloat16*)qh_p, (__nv_bfloat16*)ql_p, C3);
    }
    // 4) HMMA flash attention (Br=128, exp2 domain) -> y hi/lo bf16
    {
        dim3 grid(Tt / 128, Bb * Hh);
        flash_mma<<<grid, 256, FLASH_SMEM>>>(
            (const __nv_bfloat16*)qh_p, (const __nv_bfloat16*)ql_p,
            (__nv_bfloat16*)yh_p, (__nv_bfloat16*)yl_p);
    }
    // 5) Output projection -> out fp32
    {
        dim3 grid(Cc / 128, BT / 128);
        gemm_mma<0><<<grid, 256, GEMM_SMEM>>>(
            (const __nv_bfloat16*)yh_p, (const __nv_bfloat16*)yl_p,
            (const __nv_bfloat16*)wph_p, (const __nv_bfloat16*)wpl_p,
            b_proj, out, nullptr, nullptr, Cc);
    }
}